// round 2
// baseline (speedup 1.0000x reference)
#include <cuda_runtime.h>
#include <cuda_bf16.h>
#include <cstdint>

#define NN 50000
#define EE 400000
#define KDIM 256      // in_ch == edge_dim
#define HC   256      // heads * C
#define CH   128      // per-head channels

// ---------------- scratch (__device__ globals, no allocation) ----------------
__device__ float g_q[(size_t)NN * HC];
__device__ float g_k[(size_t)NN * HC];
__device__ float g_v[(size_t)NN * HC];
__device__ float g_e[(size_t)EE * HC];
__device__ float g_alpha[(size_t)EE * 2];
__device__ float g_amax[(size_t)NN * 2];
__device__ float g_asum[(size_t)NN * 2];

// ---------------- helpers ----------------
__device__ __forceinline__ void atomicMaxFloat(float* addr, float val) {
    // sign-split trick; addr initialized to -inf
    if (val >= 0.0f) atomicMax((int*)addr, __float_as_int(val));
    else             atomicMin((unsigned int*)addr, __float_as_uint(val));
}

// ---------------- K0: init ----------------
__global__ void init_kernel() {
    int i = blockIdx.x * blockDim.x + threadIdx.x;
    if (i < 2 * NN) {
        g_amax[i] = __int_as_float(0xff800000);  // -inf
        g_asum[i] = 0.0f;
    }
    if (i < 2 * EE) g_alpha[i] = 0.0f;
}

// ---------------- K1: node projections q/k/v + skip-out ----------------
// C[M=50000, 1024] = x[50000,256] @ [Wq|Wk|Wv|Wskip] + bias
__global__ __launch_bounds__(256) void node_proj_kernel(
    const float* __restrict__ x,
    const float* __restrict__ Wq, const float* __restrict__ bq,
    const float* __restrict__ Wk, const float* __restrict__ bk,
    const float* __restrict__ Wv, const float* __restrict__ bv,
    const float* __restrict__ Wskip, const float* __restrict__ bskip,
    float* __restrict__ out)
{
    const int nt = blockIdx.x;          // 0..15 (64-wide col tiles over 1024)
    const int m0 = blockIdx.y * 64;
    const int wsel = nt >> 2;
    const int n0 = (nt & 3) * 64;       // col within the selected 256-wide matrix

    const float* W; const float* bias; float* dst;
    switch (wsel) {
        case 0:  W = Wq;    bias = bq;    dst = g_q; break;
        case 1:  W = Wk;    bias = bk;    dst = g_k; break;
        case 2:  W = Wv;    bias = bv;    dst = g_v; break;
        default: W = Wskip; bias = bskip; dst = out; break;
    }

    __shared__ float As[16][68];   // [k][m], padded
    __shared__ float Bs[16][64];   // [k][n]

    const int t  = threadIdx.x;
    const int tx = t & 15, ty = t >> 4;
    const int arow = t >> 2;            // 0..63
    const int a4   = (t & 3) * 4;       // k sub-offset
    const int brow = t >> 4;            // 0..15
    const int b4   = (t & 15) * 4;

    int grow = m0 + arow; if (grow >= NN) grow = NN - 1;   // clamp; invalid rows never stored

    float acc[4][4] = {};

    for (int k0 = 0; k0 < KDIM; k0 += 16) {
        float4 av = *(const float4*)&x[(size_t)grow * KDIM + k0 + a4];
        As[a4 + 0][arow] = av.x; As[a4 + 1][arow] = av.y;
        As[a4 + 2][arow] = av.z; As[a4 + 3][arow] = av.w;
        float4 bvv = *(const float4*)&W[(size_t)(k0 + brow) * 256 + n0 + b4];
        *(float4*)&Bs[brow][b4] = bvv;
        __syncthreads();
        #pragma unroll
        for (int kk = 0; kk < 16; kk++) {
            float a0 = As[kk][ty * 4 + 0], a1 = As[kk][ty * 4 + 1];
            float a2 = As[kk][ty * 4 + 2], a3 = As[kk][ty * 4 + 3];
            float c0 = Bs[kk][tx * 4 + 0], c1 = Bs[kk][tx * 4 + 1];
            float c2 = Bs[kk][tx * 4 + 2], c3 = Bs[kk][tx * 4 + 3];
            acc[0][0] += a0 * c0; acc[0][1] += a0 * c1; acc[0][2] += a0 * c2; acc[0][3] += a0 * c3;
            acc[1][0] += a1 * c0; acc[1][1] += a1 * c1; acc[1][2] += a1 * c2; acc[1][3] += a1 * c3;
            acc[2][0] += a2 * c0; acc[2][1] += a2 * c1; acc[2][2] += a2 * c2; acc[2][3] += a2 * c3;
            acc[3][0] += a3 * c0; acc[3][1] += a3 * c1; acc[3][2] += a3 * c2; acc[3][3] += a3 * c3;
        }
        __syncthreads();
    }

    float4 bvv = *(const float4*)&bias[n0 + tx * 4];
    #pragma unroll
    for (int i = 0; i < 4; i++) {
        int m = m0 + ty * 4 + i;
        if (m < NN) {
            float4 o;
            o.x = acc[i][0] + bvv.x; o.y = acc[i][1] + bvv.y;
            o.z = acc[i][2] + bvv.z; o.w = acc[i][3] + bvv.w;
            *(float4*)&dst[(size_t)m * 256 + n0 + tx * 4] = o;
        }
    }
}

// ---------------- K2: edge GEMM e = edge_attr @ We, fused raw-alpha partial ----
// edge_attr[e,k] = cos(rel_t[e]*Wt[k]+bt[k]) for k<128, msg[e,k-128] for k>=128
__global__ __launch_bounds__(256) void edge_kernel(
    const float* __restrict__ last_update, const float* __restrict__ t_arr,
    const float* __restrict__ msg, const int* __restrict__ ei,
    const float* __restrict__ Wt, const float* __restrict__ bt,
    const float* __restrict__ We)
{
    const int n0 = blockIdx.x * 64;     // 0,64,128,192
    const int m0 = blockIdx.y * 64;     // edge tile base

    __shared__ float As[16][68];
    __shared__ float Bs[16][64];
    __shared__ float s_rel[64];
    __shared__ int   s_src[64], s_dst[64];
    __shared__ float s_wt[128], s_bt[128];

    const int t  = threadIdx.x;
    const int tx = t & 15, ty = t >> 4;
    const int arow = t >> 2;
    const int a4   = (t & 3) * 4;
    const int brow = t >> 4;
    const int b4   = (t & 15) * 4;

    if (t < 128) { s_wt[t] = Wt[t]; s_bt[t] = bt[t]; }
    if (t < 64) {
        int eidx = m0 + t;
        int ec = eidx < EE ? eidx : EE - 1;
        int s = ei[ec];
        int d = ei[EE + ec];
        s_src[t] = s; s_dst[t] = d;
        s_rel[t] = last_update[s] - t_arr[ec];
    }
    __syncthreads();

    float acc[4][4] = {};
    const int ecl = (m0 + arow) < EE ? (m0 + arow) : (EE - 1);

    for (int k0 = 0; k0 < KDIM; k0 += 16) {
        if (k0 < 128) {
            float rt = s_rel[arow];
            #pragma unroll
            for (int i = 0; i < 4; i++) {
                int k = k0 + a4 + i;
                As[a4 + i][arow] = __cosf(rt * s_wt[k] + s_bt[k]);
            }
        } else {
            float4 av = *(const float4*)&msg[(size_t)ecl * 128 + (k0 - 128) + a4];
            As[a4 + 0][arow] = av.x; As[a4 + 1][arow] = av.y;
            As[a4 + 2][arow] = av.z; As[a4 + 3][arow] = av.w;
        }
        float4 bvv = *(const float4*)&We[(size_t)(k0 + brow) * 256 + n0 + b4];
        *(float4*)&Bs[brow][b4] = bvv;
        __syncthreads();
        #pragma unroll
        for (int kk = 0; kk < 16; kk++) {
            float a0 = As[kk][ty * 4 + 0], a1 = As[kk][ty * 4 + 1];
            float a2 = As[kk][ty * 4 + 2], a3 = As[kk][ty * 4 + 3];
            float c0 = Bs[kk][tx * 4 + 0], c1 = Bs[kk][tx * 4 + 1];
            float c2 = Bs[kk][tx * 4 + 2], c3 = Bs[kk][tx * 4 + 3];
            acc[0][0] += a0 * c0; acc[0][1] += a0 * c1; acc[0][2] += a0 * c2; acc[0][3] += a0 * c3;
            acc[1][0] += a1 * c0; acc[1][1] += a1 * c1; acc[1][2] += a1 * c2; acc[1][3] += a1 * c3;
            acc[2][0] += a2 * c0; acc[2][1] += a2 * c1; acc[2][2] += a2 * c2; acc[2][3] += a2 * c3;
            acc[3][0] += a3 * c0; acc[3][1] += a3 * c1; acc[3][2] += a3 * c2; acc[3][3] += a3 * c3;
        }
        __syncthreads();
    }

    // epilogue: store e tile, accumulate partial raw-alpha = sum_c q[dst,c]*(k[src,c]+e[c])
    const int head = n0 >> 7;
    float part[4];
    #pragma unroll
    for (int i = 0; i < 4; i++) {
        int r = ty * 4 + i;
        int m = m0 + r;
        float p = 0.0f;
        if (m < EE) {
            int sr = s_src[r], dn = s_dst[r];
            float4 qv = *(const float4*)&g_q[(size_t)dn * 256 + n0 + tx * 4];
            float4 kv = *(const float4*)&g_k[(size_t)sr * 256 + n0 + tx * 4];
            float4 ev;
            ev.x = acc[i][0]; ev.y = acc[i][1]; ev.z = acc[i][2]; ev.w = acc[i][3];
            *(float4*)&g_e[(size_t)m * 256 + n0 + tx * 4] = ev;
            p = qv.x * (kv.x + ev.x) + qv.y * (kv.y + ev.y)
              + qv.z * (kv.z + ev.z) + qv.w * (kv.w + ev.w);
        }
        part[i] = p;
    }
    #pragma unroll
    for (int i = 0; i < 4; i++) {
        float p = part[i];
        p += __shfl_xor_sync(0xffffffffu, p, 8);
        p += __shfl_xor_sync(0xffffffffu, p, 4);
        p += __shfl_xor_sync(0xffffffffu, p, 2);
        p += __shfl_xor_sync(0xffffffffu, p, 1);
        if (tx == 0) {
            int m = m0 + ty * 4 + i;
            if (m < EE) atomicAdd(&g_alpha[(size_t)m * 2 + head], p);
        }
    }
}

// ---------------- K3: scale + segment max ----------------
__global__ void alpha_max_kernel(const int* __restrict__ ei) {
    int i = blockIdx.x * blockDim.x + threadIdx.x;
    if (i >= 2 * EE) return;
    int e = i >> 1, h = i & 1;
    float a = g_alpha[i] * 0.08838834764831845f;   // 1/sqrt(128)
    g_alpha[i] = a;
    int d = ei[EE + e];
    atomicMaxFloat(&g_amax[d * 2 + h], a);
}

// ---------------- K4: exp + segment sum ----------------
__global__ void alpha_exp_kernel(const int* __restrict__ ei) {
    int i = blockIdx.x * blockDim.x + threadIdx.x;
    if (i >= 2 * EE) return;
    int e = i >> 1, h = i & 1;
    int d = ei[EE + e];
    float w = __expf(g_alpha[i] - g_amax[d * 2 + h]);
    g_alpha[i] = w;
    atomicAdd(&g_asum[d * 2 + h], w);
}

// ---------------- K5: weighted aggregate (one warp per edge) ----------------
__global__ __launch_bounds__(256) void aggregate_kernel(
    const int* __restrict__ ei, float* __restrict__ out)
{
    int warp = (int)((blockIdx.x * (unsigned)blockDim.x + threadIdx.x) >> 5);
    int lane = threadIdx.x & 31;
    if (warp >= EE) return;
    int e = warp;
    int s = ei[e];
    int d = ei[EE + e];
    int col = lane * 8;
    int h = col >> 7;
    float coef = g_alpha[(size_t)e * 2 + h] / (g_asum[d * 2 + h] + 1e-16f);
    const float4* vp = (const float4*)&g_v[(size_t)s * 256 + col];
    const float4* ep = (const float4*)&g_e[(size_t)e * 256 + col];
    float* op = &out[(size_t)d * 256 + col];
    #pragma unroll
    for (int r = 0; r < 2; r++) {
        float4 vv = vp[r];
        float4 ev = ep[r];
        atomicAdd(op + r * 4 + 0, (vv.x + ev.x) * coef);
        atomicAdd(op + r * 4 + 1, (vv.y + ev.y) * coef);
        atomicAdd(op + r * 4 + 2, (vv.z + ev.z) * coef);
        atomicAdd(op + r * 4 + 3, (vv.w + ev.w) * coef);
    }
}

// ---------------- launcher ----------------
extern "C" void kernel_launch(void* const* d_in, const int* in_sizes, int n_in,
                              void* d_out, int out_size) {
    const float* x           = (const float*)d_in[0];
    const float* last_update = (const float*)d_in[1];
    const float* t_arr       = (const float*)d_in[2];
    const float* msg         = (const float*)d_in[3];
    const int*   ei          = (const int*)d_in[4];
    const float* Wt          = (const float*)d_in[5];
    const float* bt          = (const float*)d_in[6];
    const float* Wq          = (const float*)d_in[7];
    const float* bq          = (const float*)d_in[8];
    const float* Wk          = (const float*)d_in[9];
    const float* bk          = (const float*)d_in[10];
    const float* Wv          = (const float*)d_in[11];
    const float* bv          = (const float*)d_in[12];
    const float* We          = (const float*)d_in[13];
    const float* Wskip       = (const float*)d_in[14];
    const float* bskip       = (const float*)d_in[15];
    float* out = (float*)d_out;

    init_kernel<<<(2 * EE + 255) / 256, 256>>>();

    dim3 g1(16, (NN + 63) / 64);
    node_proj_kernel<<<g1, 256>>>(x, Wq, bq, Wk, bk, Wv, bv, Wskip, bskip, out);

    dim3 g2(4, (EE + 63) / 64);
    edge_kernel<<<g2, 256>>>(last_update, t_arr, msg, ei, Wt, bt, We);

    alpha_max_kernel<<<(2 * EE + 255) / 256, 256>>>(ei);
    alpha_exp_kernel<<<(2 * EE + 255) / 256, 256>>>(ei);

    aggregate_kernel<<<(EE * 32 + 255) / 256, 256>>>(ei, out);
}

// round 4
// speedup vs baseline: 1.5916x; 1.5916x over previous
#include <cuda_runtime.h>
#include <cuda_bf16.h>
#include <cstdint>

#define NN 50000
#define EE 400000
#define KDIM 256
#define HC   256
#define CH   128

// ---------------- scratch ----------------
__device__ float g_q[(size_t)NN * HC];
__device__ float g_k[(size_t)NN * HC];
__device__ float g_v[(size_t)NN * HC];
__device__ float g_e[(size_t)EE * HC];
__device__ float g_alpha[(size_t)EE * 2];
__device__ float g_amax[(size_t)NN * 2];
__device__ float g_asum[(size_t)NN * 2];

// ---------------- helpers ----------------
__device__ __forceinline__ void atomicMaxFloat(float* addr, float val) {
    if (val >= 0.0f) atomicMax((int*)addr, __float_as_int(val));
    else             atomicMin((unsigned int*)addr, __float_as_uint(val));
}

__device__ __forceinline__ void split2(float v0, float v1, uint32_t& hw, uint32_t& lw) {
    __nv_bfloat16 h0 = __float2bfloat16(v0), h1 = __float2bfloat16(v1);
    float r0 = v0 - __bfloat162float(h0), r1 = v1 - __bfloat162float(h1);
    __nv_bfloat162 hh; hh.x = h0; hh.y = h1;
    __nv_bfloat162 ll; ll.x = __float2bfloat16(r0); ll.y = __float2bfloat16(r1);
    hw = *reinterpret_cast<uint32_t*>(&hh);
    lw = *reinterpret_cast<uint32_t*>(&ll);
}

__device__ __forceinline__ void mma_bf16(float* c, const uint32_t* a, const uint32_t* b) {
    asm volatile(
        "mma.sync.aligned.m16n8k16.row.col.f32.bf16.bf16.f32 "
        "{%0,%1,%2,%3}, {%4,%5,%6,%7}, {%8,%9}, {%0,%1,%2,%3};"
        : "+f"(c[0]), "+f"(c[1]), "+f"(c[2]), "+f"(c[3])
        : "r"(a[0]), "r"(a[1]), "r"(a[2]), "r"(a[3]), "r"(b[0]), "r"(b[1]));
}

// ---------------- K0: init ----------------
__global__ void init_kernel() {
    int i = blockIdx.x * blockDim.x + threadIdx.x;
    if (i < 2 * NN) {
        g_amax[i] = __int_as_float(0xff800000);
        g_asum[i] = 0.0f;
    }
}

// =====================================================================
// Tensor-core GEMM tiles: BM=128, BN=64, BK=32, 256 threads (8 warps,
// 4x2 warp grid, 32x32 per warp). A[m][k] / B^T[n][k] stored as packed
// bf16-pair words, row stride 20 words (conflict-free fragment reads).
// 3 mma terms: Ah*Bh + Ah*Bl + Al*Bh.
// =====================================================================
#define ASTRIDE 20
#define BSTRIDE 20

struct GemmSmem {
    uint32_t AhW[128 * ASTRIDE];
    uint32_t AlW[128 * ASTRIDE];
    uint32_t BhW[64 * BSTRIDE];
    uint32_t BlW[64 * BSTRIDE];
};

__device__ __forceinline__ void gemm_fill_B(GemmSmem& s, const float* __restrict__ W,
                                            int kt, int n0, int t) {
    int n = t & 63;
    int kp0 = t >> 6;
    #pragma unroll
    for (int jj = 0; jj < 4; jj++) {
        int kp = jj * 4 + kp0;
        int k = kt * 32 + kp * 2;
        float v0 = W[(size_t)k * 256 + n0 + n];
        float v1 = W[(size_t)(k + 1) * 256 + n0 + n];
        uint32_t hw, lw;
        split2(v0, v1, hw, lw);
        s.BhW[n * BSTRIDE + kp] = hw;
        s.BlW[n * BSTRIDE + kp] = lw;
    }
}

__device__ __forceinline__ void gemm_compute(GemmSmem& s, float acc[2][4][4],
                                             int wm, int wn, int g, int i) {
    #pragma unroll
    for (int ks = 0; ks < 2; ks++) {
        int kb = ks * 8;
        uint32_t ah[2][4], al[2][4];
        #pragma unroll
        for (int mm = 0; mm < 2; mm++) {
            int r = wm * 32 + mm * 16;
            ah[mm][0] = s.AhW[(r + g) * ASTRIDE + kb + i];
            ah[mm][1] = s.AhW[(r + g + 8) * ASTRIDE + kb + i];
            ah[mm][2] = s.AhW[(r + g) * ASTRIDE + kb + i + 4];
            ah[mm][3] = s.AhW[(r + g + 8) * ASTRIDE + kb + i + 4];
            al[mm][0] = s.AlW[(r + g) * ASTRIDE + kb + i];
            al[mm][1] = s.AlW[(r + g + 8) * ASTRIDE + kb + i];
            al[mm][2] = s.AlW[(r + g) * ASTRIDE + kb + i + 4];
            al[mm][3] = s.AlW[(r + g + 8) * ASTRIDE + kb + i + 4];
        }
        uint32_t bh[4][2], bl[4][2];
        #pragma unroll
        for (int nn = 0; nn < 4; nn++) {
            int c = wn * 32 + nn * 8 + g;
            bh[nn][0] = s.BhW[c * BSTRIDE + kb + i];
            bh[nn][1] = s.BhW[c * BSTRIDE + kb + i + 4];
            bl[nn][0] = s.BlW[c * BSTRIDE + kb + i];
            bl[nn][1] = s.BlW[c * BSTRIDE + kb + i + 4];
        }
        #pragma unroll
        for (int mm = 0; mm < 2; mm++)
            #pragma unroll
            for (int nn = 0; nn < 4; nn++) {
                mma_bf16(acc[mm][nn], ah[mm], bh[nn]);
                mma_bf16(acc[mm][nn], ah[mm], bl[nn]);
                mma_bf16(acc[mm][nn], al[mm], bh[nn]);
            }
    }
}

// ---------------- K1: node projections (tensor) ----------------
__global__ __launch_bounds__(256) void node_proj_kernel(
    const float* __restrict__ x,
    const float* __restrict__ Wq, const float* __restrict__ bq,
    const float* __restrict__ Wk, const float* __restrict__ bk,
    const float* __restrict__ Wv, const float* __restrict__ bv,
    const float* __restrict__ Wskip, const float* __restrict__ bskip,
    float* __restrict__ out)
{
    __shared__ GemmSmem s;
    const int bx = blockIdx.x;
    const int wsel = bx >> 2;
    const int n0 = (bx & 3) * 64;
    const int m0 = blockIdx.y * 128;

    const float* W; const float* bias; float* dst;
    switch (wsel) {
        case 0:  W = Wq;    bias = bq;    dst = g_q; break;
        case 1:  W = Wk;    bias = bk;    dst = g_k; break;
        case 2:  W = Wv;    bias = bv;    dst = g_v; break;
        default: W = Wskip; bias = bskip; dst = out; break;
    }

    const int t = threadIdx.x;
    const int warp = t >> 5, lane = t & 31;
    const int wm = warp >> 1, wn = warp & 1;
    const int g = lane >> 2, i = lane & 3;

    const int arow = t >> 1, half = t & 1;
    int rowg = m0 + arow; if (rowg >= NN) rowg = NN - 1;

    float acc[2][4][4];
    #pragma unroll
    for (int mm = 0; mm < 2; mm++)
        #pragma unroll
        for (int nn = 0; nn < 4; nn++)
            #pragma unroll
            for (int r = 0; r < 4; r++) acc[mm][nn][r] = 0.0f;

    for (int kt = 0; kt < 8; kt++) {
        // A fill: 16 values per thread
        float vals[16];
        const float4* ap = (const float4*)&x[(size_t)rowg * 256 + kt * 32 + half * 16];
        #pragma unroll
        for (int q4 = 0; q4 < 4; q4++) {
            float4 v = ap[q4];
            vals[q4 * 4 + 0] = v.x; vals[q4 * 4 + 1] = v.y;
            vals[q4 * 4 + 2] = v.z; vals[q4 * 4 + 3] = v.w;
        }
        #pragma unroll
        for (int j = 0; j < 8; j++) {
            uint32_t hw, lw;
            split2(vals[2 * j], vals[2 * j + 1], hw, lw);
            s.AhW[arow * ASTRIDE + half * 8 + j] = hw;
            s.AlW[arow * ASTRIDE + half * 8 + j] = lw;
        }
        gemm_fill_B(s, W, kt, n0, t);
        __syncthreads();
        gemm_compute(s, acc, wm, wn, g, i);
        __syncthreads();
    }

    #pragma unroll
    for (int mm = 0; mm < 2; mm++) {
        #pragma unroll
        for (int nn = 0; nn < 4; nn++) {
            int cc = n0 + wn * 32 + nn * 8 + i * 2;
            float2 bv2 = *(const float2*)&bias[cc];
            int r0 = m0 + wm * 32 + mm * 16 + g;
            if (r0 < NN) {
                float2 o; o.x = acc[mm][nn][0] + bv2.x; o.y = acc[mm][nn][1] + bv2.y;
                *(float2*)&dst[(size_t)r0 * 256 + cc] = o;
            }
            if (r0 + 8 < NN) {
                float2 o; o.x = acc[mm][nn][2] + bv2.x; o.y = acc[mm][nn][3] + bv2.y;
                *(float2*)&dst[(size_t)(r0 + 8) * 256 + cc] = o;
            }
        }
    }
}

// ---------------- K2: edge GEMM (tensor) ----------------
__global__ __launch_bounds__(256) void edge_kernel(
    const float* __restrict__ last_update, const float* __restrict__ t_arr,
    const float* __restrict__ msg, const int* __restrict__ ei,
    const float* __restrict__ Wt, const float* __restrict__ bt,
    const float* __restrict__ We)
{
    __shared__ GemmSmem s;
    __shared__ float s_rel[128];
    __shared__ float s_wt[128], s_bt[128];

    const int n0 = blockIdx.x * 64;
    const int m0 = blockIdx.y * 128;

    const int t = threadIdx.x;
    const int warp = t >> 5, lane = t & 31;
    const int wm = warp >> 1, wn = warp & 1;
    const int g = lane >> 2, i = lane & 3;
    const int arow = t >> 1, half = t & 1;
    const int eg = m0 + arow;   // EE divisible by 128

    if (t < 128) {
        s_wt[t] = Wt[t]; s_bt[t] = bt[t];
        int e = m0 + t;
        s_rel[t] = last_update[ei[e]] - t_arr[e];
    }
    __syncthreads();

    const float rel = s_rel[arow];

    float acc[2][4][4];
    #pragma unroll
    for (int mm = 0; mm < 2; mm++)
        #pragma unroll
        for (int nn = 0; nn < 4; nn++)
            #pragma unroll
            for (int r = 0; r < 4; r++) acc[mm][nn][r] = 0.0f;

    for (int kt = 0; kt < 8; kt++) {
        float vals[16];
        if (kt < 4) {
            #pragma unroll
            for (int j = 0; j < 16; j++) {
                int k = kt * 32 + half * 16 + j;
                vals[j] = __cosf(rel * s_wt[k] + s_bt[k]);
            }
        } else {
            const float4* mp = (const float4*)&msg[(size_t)eg * 128 + (kt - 4) * 32 + half * 16];
            #pragma unroll
            for (int q4 = 0; q4 < 4; q4++) {
                float4 v = mp[q4];
                vals[q4 * 4 + 0] = v.x; vals[q4 * 4 + 1] = v.y;
                vals[q4 * 4 + 2] = v.z; vals[q4 * 4 + 3] = v.w;
            }
        }
        #pragma unroll
        for (int j = 0; j < 8; j++) {
            uint32_t hw, lw;
            split2(vals[2 * j], vals[2 * j + 1], hw, lw);
            s.AhW[arow * ASTRIDE + half * 8 + j] = hw;
            s.AlW[arow * ASTRIDE + half * 8 + j] = lw;
        }
        gemm_fill_B(s, We, kt, n0, t);
        __syncthreads();
        gemm_compute(s, acc, wm, wn, g, i);
        __syncthreads();
    }

    #pragma unroll
    for (int mm = 0; mm < 2; mm++) {
        #pragma unroll
        for (int nn = 0; nn < 4; nn++) {
            int cc = n0 + wn * 32 + nn * 8 + i * 2;
            int r0 = m0 + wm * 32 + mm * 16 + g;
            float2 o0; o0.x = acc[mm][nn][0]; o0.y = acc[mm][nn][1];
            float2 o1; o1.x = acc[mm][nn][2]; o1.y = acc[mm][nn][3];
            *(float2*)&g_e[(size_t)r0 * 256 + cc] = o0;
            *(float2*)&g_e[(size_t)(r0 + 8) * 256 + cc] = o1;
        }
    }
}

// ---------------- K3: alpha = q[dst].(k[src]+e)/sqrt(C), segment max ----
__global__ __launch_bounds__(256) void alpha_kernel(const int* __restrict__ ei) {
    int e = blockIdx.x * 8 + (threadIdx.x >> 5);
    int lane = threadIdx.x & 31;
    if (e >= EE) return;
    int sidx = ei[e];
    int didx = ei[EE + e];
    int c0 = lane * 8;
    const float4* ep = (const float4*)&g_e[(size_t)e * 256 + c0];
    const float4* kp = (const float4*)&g_k[(size_t)sidx * 256 + c0];
    const float4* qp = (const float4*)&g_q[(size_t)didx * 256 + c0];
    float p = 0.0f;
    #pragma unroll
    for (int r = 0; r < 2; r++) {
        float4 ev = ep[r], kv = kp[r], qv = qp[r];
        p += qv.x * (kv.x + ev.x) + qv.y * (kv.y + ev.y)
           + qv.z * (kv.z + ev.z) + qv.w * (kv.w + ev.w);
    }
    p += __shfl_xor_sync(0xffffffffu, p, 8);
    p += __shfl_xor_sync(0xffffffffu, p, 4);
    p += __shfl_xor_sync(0xffffffffu, p, 2);
    p += __shfl_xor_sync(0xffffffffu, p, 1);
    if ((lane & 15) == 0) {
        int h = lane >> 4;
        float a = p * 0.08838834764831845f;
        g_alpha[(size_t)e * 2 + h] = a;
        atomicMaxFloat(&g_amax[didx * 2 + h], a);
    }
}

// ---------------- K4: exp + segment sum ----------------
__global__ void alpha_exp_kernel(const int* __restrict__ ei) {
    int idx = blockIdx.x * blockDim.x + threadIdx.x;
    if (idx >= 2 * EE) return;
    int e = idx >> 1, h = idx & 1;
    int d = ei[EE + e];
    float w = __expf(g_alpha[idx] - g_amax[d * 2 + h]);
    g_alpha[idx] = w;
    atomicAdd(&g_asum[d * 2 + h], w);
}

// ---------------- K5: weighted aggregate ----------------
__global__ __launch_bounds__(256) void aggregate_kernel(
    const int* __restrict__ ei, float* __restrict__ out)
{
    int warp = (int)((blockIdx.x * (unsigned)blockDim.x + threadIdx.x) >> 5);
    int lane = threadIdx.x & 31;
    if (warp >= EE) return;
    int e = warp;
    int sidx = ei[e];
    int didx = ei[EE + e];
    int col = lane * 8;
    int h = col >> 7;
    float coef = g_alpha[(size_t)e * 2 + h] / (g_asum[didx * 2 + h] + 1e-16f);
    const float4* vp = (const float4*)&g_v[(size_t)sidx * 256 + col];
    const float4* ep = (const float4*)&g_e[(size_t)e * 256 + col];
    float* op = &out[(size_t)didx * 256 + col];
    #pragma unroll
    for (int r = 0; r < 2; r++) {
        float4 vv = vp[r];
        float4 ev = ep[r];
        atomicAdd(op + r * 4 + 0, (vv.x + ev.x) * coef);
        atomicAdd(op + r * 4 + 1, (vv.y + ev.y) * coef);
        atomicAdd(op + r * 4 + 2, (vv.z + ev.z) * coef);
        atomicAdd(op + r * 4 + 3, (vv.w + ev.w) * coef);
    }
}

// ---------------- launcher ----------------
extern "C" void kernel_launch(void* const* d_in, const int* in_sizes, int n_in,
                              void* d_out, int out_size) {
    const float* x           = (const float*)d_in[0];
    const float* last_update = (const float*)d_in[1];
    const float* t_arr       = (const float*)d_in[2];
    const float* msg         = (const float*)d_in[3];
    const int*   ei          = (const int*)d_in[4];
    const float* Wt          = (const float*)d_in[5];
    const float* bt          = (const float*)d_in[6];
    const float* Wq          = (const float*)d_in[7];
    const float* bq          = (const float*)d_in[8];
    const float* Wk          = (const float*)d_in[9];
    const float* bk          = (const float*)d_in[10];
    const float* Wv          = (const float*)d_in[11];
    const float* bv          = (const float*)d_in[12];
    const float* We          = (const float*)d_in[13];
    const float* Wskip       = (const float*)d_in[14];
    const float* bskip       = (const float*)d_in[15];
    float* out = (float*)d_out;

    init_kernel<<<(2 * NN + 255) / 256, 256>>>();

    dim3 g1(16, (NN + 127) / 128);
    node_proj_kernel<<<g1, 256>>>(x, Wq, bq, Wk, bk, Wv, bv, Wskip, bskip, out);

    dim3 g2(4, EE / 128);
    edge_kernel<<<g2, 256>>>(last_update, t_arr, msg, ei, Wt, bt, We);

    alpha_kernel<<<EE / 8, 256>>>(ei);
    alpha_exp_kernel<<<(2 * EE + 255) / 256, 256>>>(ei);
    aggregate_kernel<<<(EE * 32 + 255) / 256, 256>>>(ei, out);
}

// round 7
// speedup vs baseline: 2.5052x; 1.5740x over previous
#include <cuda_runtime.h>
#include <cuda_bf16.h>
#include <cstdint>

#define NN 50000
#define EE 400000

// ---------------- scratch ----------------
__device__ float g_q[(size_t)NN * 256];
__device__ float g_k[(size_t)NN * 256];
__device__ float g_v[(size_t)NN * 256];
__device__ float g_e[(size_t)EE * 256];
__device__ float g_alpha[(size_t)EE * 2];
__device__ float g_amax[(size_t)NN * 2];
__device__ float g_asum[(size_t)NN * 2];

// ---------------- helpers ----------------
__device__ __forceinline__ void atomicMaxFloat(float* addr, float val) {
    if (val >= 0.0f) atomicMax((int*)addr, __float_as_int(val));
    else             atomicMin((unsigned int*)addr, __float_as_uint(val));
}

__device__ __forceinline__ float to_tf32(float x) {
    float r; asm("cvt.rna.tf32.f32 %0, %1;" : "=f"(r) : "f"(x)); return r;
}

__device__ __forceinline__ void mma_tf32(float* c, const float* a, const float* b) {
    asm volatile(
        "mma.sync.aligned.m16n8k8.row.col.f32.tf32.tf32.f32 "
        "{%0,%1,%2,%3}, {%4,%5,%6,%7}, {%8,%9}, {%0,%1,%2,%3};"
        : "+f"(c[0]), "+f"(c[1]), "+f"(c[2]), "+f"(c[3])
        : "r"(__float_as_uint(a[0])), "r"(__float_as_uint(a[1])),
          "r"(__float_as_uint(a[2])), "r"(__float_as_uint(a[3])),
          "r"(__float_as_uint(b[0])), "r"(__float_as_uint(b[1])));
}

// ---------------- K0: init ----------------
__global__ void init_kernel() {
    int i = blockIdx.x * blockDim.x + threadIdx.x;
    if (i < 2 * NN) {
        g_amax[i] = __int_as_float(0xff800000);
        g_asum[i] = 0.0f;
    }
    if (i < 2 * EE) g_alpha[i] = 0.0f;
}

// =====================================================================
// tf32 GEMM tile: BM=128, BN=64, BK=32, 8 warps (4x2), 32x32 per warp.
// Smem stride 36 floats -> conflict-free fragment LDS for (g,i) pattern.
// =====================================================================
#define ASTR 36
#define BSTR 36

struct GemmSmem {
    float A[128 * ASTR];
    float B[64 * BSTR];
};

__device__ __forceinline__ void gemm_fill_B(GemmSmem& s, const float* __restrict__ W,
                                            int kt, int n0, int t) {
    int n = t & 63;
    int kp0 = t >> 6;                 // 0..3, covers 8 k each
    int kbase = kt * 32 + kp0 * 8;
    #pragma unroll
    for (int j = 0; j < 8; j++) {
        s.B[n * BSTR + kp0 * 8 + j] = to_tf32(W[(size_t)(kbase + j) * 256 + n0 + n]);
    }
}

__device__ __forceinline__ void gemm_compute(GemmSmem& s, float acc[2][4][4],
                                             int wm, int wn, int g, int i) {
    #pragma unroll
    for (int ks = 0; ks < 4; ks++) {
        int kb = ks * 8;
        float a[2][4];
        #pragma unroll
        for (int mm = 0; mm < 2; mm++) {
            int r = (wm * 32 + mm * 16 + g) * ASTR;
            a[mm][0] = s.A[r + kb + i];
            a[mm][1] = s.A[r + 8 * ASTR + kb + i];
            a[mm][2] = s.A[r + kb + i + 4];
            a[mm][3] = s.A[r + 8 * ASTR + kb + i + 4];
        }
        float b[4][2];
        #pragma unroll
        for (int nn = 0; nn < 4; nn++) {
            int cb = (wn * 32 + nn * 8 + g) * BSTR;
            b[nn][0] = s.B[cb + kb + i];
            b[nn][1] = s.B[cb + kb + i + 4];
        }
        #pragma unroll
        for (int mm = 0; mm < 2; mm++)
            #pragma unroll
            for (int nn = 0; nn < 4; nn++)
                mma_tf32(acc[mm][nn], a[mm], b[nn]);
    }
}

// ---------------- K1: node projections (tf32 tensor) ----------------
__global__ __launch_bounds__(256) void node_proj_kernel(
    const float* __restrict__ x,
    const float* __restrict__ Wq, const float* __restrict__ bq,
    const float* __restrict__ Wk, const float* __restrict__ bk,
    const float* __restrict__ Wv, const float* __restrict__ bv,
    const float* __restrict__ Wskip, const float* __restrict__ bskip,
    float* __restrict__ out)
{
    __shared__ GemmSmem s;
    const int bx = blockIdx.x;
    const int wsel = bx >> 2;
    const int n0 = (bx & 3) * 64;
    const int m0 = blockIdx.y * 128;

    const float* W; const float* bias; float* dst;
    switch (wsel) {
        case 0:  W = Wq;    bias = bq;    dst = g_q; break;
        case 1:  W = Wk;    bias = bk;    dst = g_k; break;
        case 2:  W = Wv;    bias = bv;    dst = g_v; break;
        default: W = Wskip; bias = bskip; dst = out; break;
    }

    const int t = threadIdx.x;
    const int warp = t >> 5, lane = t & 31;
    const int wm = warp >> 1, wn = warp & 1;
    const int g = lane >> 2, i = lane & 3;
    const int arow = t >> 1, half = t & 1;
    int rowg = m0 + arow; if (rowg >= NN) rowg = NN - 1;

    float acc[2][4][4];
    #pragma unroll
    for (int mm = 0; mm < 2; mm++)
        #pragma unroll
        for (int nn = 0; nn < 4; nn++)
            #pragma unroll
            for (int r = 0; r < 4; r++) acc[mm][nn][r] = 0.0f;

    for (int kt = 0; kt < 8; kt++) {
        const float4* ap = (const float4*)&x[(size_t)rowg * 256 + kt * 32 + half * 16];
        #pragma unroll
        for (int q4 = 0; q4 < 4; q4++) {
            float4 v = ap[q4];
            float4 o; o.x = to_tf32(v.x); o.y = to_tf32(v.y);
            o.z = to_tf32(v.z); o.w = to_tf32(v.w);
            *(float4*)&s.A[arow * ASTR + half * 16 + q4 * 4] = o;
        }
        gemm_fill_B(s, W, kt, n0, t);
        __syncthreads();
        gemm_compute(s, acc, wm, wn, g, i);
        __syncthreads();
    }

    #pragma unroll
    for (int mm = 0; mm < 2; mm++) {
        #pragma unroll
        for (int nn = 0; nn < 4; nn++) {
            int cc = n0 + wn * 32 + nn * 8 + i * 2;
            float2 bv2 = *(const float2*)&bias[cc];
            int r0 = m0 + wm * 32 + mm * 16 + g;
            if (r0 < NN) {
                float2 o; o.x = acc[mm][nn][0] + bv2.x; o.y = acc[mm][nn][1] + bv2.y;
                *(float2*)&dst[(size_t)r0 * 256 + cc] = o;
            }
            if (r0 + 8 < NN) {
                float2 o; o.x = acc[mm][nn][2] + bv2.x; o.y = acc[mm][nn][3] + bv2.y;
                *(float2*)&dst[(size_t)(r0 + 8) * 256 + cc] = o;
            }
        }
    }
}

// ---------------- K2: edge GEMM (tf32) + fused alpha partials ----------------
__global__ __launch_bounds__(256) void edge_kernel(
    const float* __restrict__ last_update, const float* __restrict__ t_arr,
    const float* __restrict__ msg, const int* __restrict__ ei,
    const float* __restrict__ Wt, const float* __restrict__ bt,
    const float* __restrict__ We)
{
    __shared__ GemmSmem s;
    __shared__ float s_rel[128];
    __shared__ int   s_src[128], s_dst[128];
    __shared__ float s_wt[128], s_bt[128];

    const int n0 = blockIdx.x * 64;
    const int m0 = blockIdx.y * 128;

    const int t = threadIdx.x;
    const int warp = t >> 5, lane = t & 31;
    const int wm = warp >> 1, wn = warp & 1;
    const int g = lane >> 2, i = lane & 3;
    const int arow = t >> 1, half = t & 1;
    const int eg = m0 + arow;     // EE divisible by 128

    if (t < 128) {
        s_wt[t] = Wt[t]; s_bt[t] = bt[t];
        int e = m0 + t;
        int sidx = ei[e];
        s_src[t] = sidx;
        s_dst[t] = ei[EE + e];
        s_rel[t] = last_update[sidx] - t_arr[e];
    }
    __syncthreads();

    const float rel = s_rel[arow];

    float acc[2][4][4];
    #pragma unroll
    for (int mm = 0; mm < 2; mm++)
        #pragma unroll
        for (int nn = 0; nn < 4; nn++)
            #pragma unroll
            for (int r = 0; r < 4; r++) acc[mm][nn][r] = 0.0f;

    for (int kt = 0; kt < 8; kt++) {
        if (kt < 4) {
            #pragma unroll
            for (int q4 = 0; q4 < 4; q4++) {
                float4 o;
                int k = kt * 32 + half * 16 + q4 * 4;
                o.x = to_tf32(__cosf(rel * s_wt[k + 0] + s_bt[k + 0]));
                o.y = to_tf32(__cosf(rel * s_wt[k + 1] + s_bt[k + 1]));
                o.z = to_tf32(__cosf(rel * s_wt[k + 2] + s_bt[k + 2]));
                o.w = to_tf32(__cosf(rel * s_wt[k + 3] + s_bt[k + 3]));
                *(float4*)&s.A[arow * ASTR + half * 16 + q4 * 4] = o;
            }
        } else {
            const float4* mp = (const float4*)&msg[(size_t)eg * 128 + (kt - 4) * 32 + half * 16];
            #pragma unroll
            for (int q4 = 0; q4 < 4; q4++) {
                float4 v = mp[q4];
                float4 o; o.x = to_tf32(v.x); o.y = to_tf32(v.y);
                o.z = to_tf32(v.z); o.w = to_tf32(v.w);
                *(float4*)&s.A[arow * ASTR + half * 16 + q4 * 4] = o;
            }
        }
        gemm_fill_B(s, We, kt, n0, t);
        __syncthreads();
        gemm_compute(s, acc, wm, wn, g, i);
        __syncthreads();
    }

    // epilogue: store e; fused partial raw-alpha = sum_c q[dst,c]*(k[src,c]+e[c])
    const int head = n0 >> 7;
    #pragma unroll
    for (int mm = 0; mm < 2; mm++) {
        int lr = wm * 32 + mm * 16 + g;
        int e0 = m0 + lr, e1 = e0 + 8;
        int s0 = s_src[lr], d0 = s_dst[lr];
        int s1 = s_src[lr + 8], d1 = s_dst[lr + 8];
        float pa = 0.0f, pb = 0.0f;
        #pragma unroll
        for (int nn = 0; nn < 4; nn++) {
            int cc = n0 + wn * 32 + nn * 8 + i * 2;
            float2 ev0; ev0.x = acc[mm][nn][0]; ev0.y = acc[mm][nn][1];
            float2 ev1; ev1.x = acc[mm][nn][2]; ev1.y = acc[mm][nn][3];
            *(float2*)&g_e[(size_t)e0 * 256 + cc] = ev0;
            *(float2*)&g_e[(size_t)e1 * 256 + cc] = ev1;
            float2 q0 = *(const float2*)&g_q[(size_t)d0 * 256 + cc];
            float2 k0 = *(const float2*)&g_k[(size_t)s0 * 256 + cc];
            float2 q1 = *(const float2*)&g_q[(size_t)d1 * 256 + cc];
            float2 k1 = *(const float2*)&g_k[(size_t)s1 * 256 + cc];
            pa += q0.x * (k0.x + ev0.x) + q0.y * (k0.y + ev0.y);
            pb += q1.x * (k1.x + ev1.x) + q1.y * (k1.y + ev1.y);
        }
        pa += __shfl_xor_sync(0xffffffffu, pa, 1);
        pa += __shfl_xor_sync(0xffffffffu, pa, 2);
        pb += __shfl_xor_sync(0xffffffffu, pb, 1);
        pb += __shfl_xor_sync(0xffffffffu, pb, 2);
        if (i == 0) {
            atomicAdd(&g_alpha[(size_t)e0 * 2 + head], pa);
            atomicAdd(&g_alpha[(size_t)e1 * 2 + head], pb);
        }
    }
}

// ---------------- K3: scale + segment max ----------------
__global__ void alpha_max_kernel(const int* __restrict__ ei) {
    int idx = blockIdx.x * blockDim.x + threadIdx.x;
    if (idx >= 2 * EE) return;
    int e = idx >> 1, h = idx & 1;
    float a = g_alpha[idx] * 0.08838834764831845f;   // 1/sqrt(128)
    g_alpha[idx] = a;
    atomicMaxFloat(&g_amax[ei[EE + e] * 2 + h], a);
}

// ---------------- K4: exp + segment sum ----------------
__global__ void alpha_exp_kernel(const int* __restrict__ ei) {
    int idx = blockIdx.x * blockDim.x + threadIdx.x;
    if (idx >= 2 * EE) return;
    int e = idx >> 1, h = idx & 1;
    int d = ei[EE + e];
    float w = __expf(g_alpha[idx] - g_amax[d * 2 + h]);
    g_alpha[idx] = w;
    atomicAdd(&g_asum[d * 2 + h], w);
}

// ---------------- K5: weighted aggregate (vector RED) ----------------
__global__ __launch_bounds__(256) void aggregate_kernel(
    const int* __restrict__ ei, float* __restrict__ out)
{
    int warp = (int)((blockIdx.x * (unsigned)blockDim.x + threadIdx.x) >> 5);
    int lane = threadIdx.x & 31;
    if (warp >= EE) return;
    int e = warp;
    int sidx = ei[e];
    int didx = ei[EE + e];
    int col = lane * 8;
    int h = col >> 7;
    float coef = g_alpha[(size_t)e * 2 + h] / (g_asum[didx * 2 + h] + 1e-16f);
    const float4* vp = (const float4*)&g_v[(size_t)sidx * 256 + col];
    const float4* ep = (const float4*)&g_e[(size_t)e * 256 + col];
    float* op = &out[(size_t)didx * 256 + col];
    #pragma unroll
    for (int r = 0; r < 2; r++) {
        float4 vv = vp[r];
        float4 ev = ep[r];
        float a0 = (vv.x + ev.x) * coef;
        float a1 = (vv.y + ev.y) * coef;
        float a2 = (vv.z + ev.z) * coef;
        float a3 = (vv.w + ev.w) * coef;
        asm volatile("red.global.add.v4.f32 [%0], {%1, %2, %3, %4};"
                     :: "l"(op + r * 4), "f"(a0), "f"(a1), "f"(a2), "f"(a3)
                     : "memory");
    }
}

// ---------------- launcher ----------------
extern "C" void kernel_launch(void* const* d_in, const int* in_sizes, int n_in,
                              void* d_out, int out_size) {
    const float* x           = (const float*)d_in[0];
    const float* last_update = (const float*)d_in[1];
    const float* t_arr       = (const float*)d_in[2];
    const float* msg         = (const float*)d_in[3];
    const int*   ei          = (const int*)d_in[4];
    const float* Wt          = (const float*)d_in[5];
    const float* bt          = (const float*)d_in[6];
    const float* Wq          = (const float*)d_in[7];
    const float* bq          = (const float*)d_in[8];
    const float* Wk          = (const float*)d_in[9];
    const float* bk          = (const float*)d_in[10];
    const float* Wv          = (const float*)d_in[11];
    const float* bv          = (const float*)d_in[12];
    const float* We          = (const float*)d_in[13];
    const float* Wskip       = (const float*)d_in[14];
    const float* bskip       = (const float*)d_in[15];
    float* out = (float*)d_out;

    init_kernel<<<(2 * EE + 255) / 256, 256>>>();

    dim3 g1(16, (NN + 127) / 128);
    node_proj_kernel<<<g1, 256>>>(x, Wq, bq, Wk, bk, Wv, bv, Wskip, bskip, out);

    dim3 g2(4, EE / 128);
    edge_kernel<<<g2, 256>>>(last_update, t_arr, msg, ei, Wt, bt, We);

    alpha_max_kernel<<<(2 * EE + 255) / 256, 256>>>(ei);
    alpha_exp_kernel<<<(2 * EE + 255) / 256, 256>>>(ei);
    aggregate_kernel<<<(EE * 32 + 255) / 256, 256>>>(ei, out);
}

// round 9
// speedup vs baseline: 2.6688x; 1.0653x over previous
#include <cuda_runtime.h>
#include <cuda_bf16.h>
#include <cstdint>

#define NN 50000
#define EE 400000

// ---------------- scratch ----------------
__device__ float g_q[(size_t)NN * 256];
__device__ float g_k[(size_t)NN * 256];
__device__ float g_v[(size_t)NN * 256];
__device__ float g_e[(size_t)EE * 256];
__device__ float g_alpha[(size_t)EE * 2];
__device__ float g_amax[(size_t)NN * 2];
__device__ float g_asum[(size_t)NN * 2];

// ---------------- helpers ----------------
__device__ __forceinline__ void atomicMaxFloat(float* addr, float val) {
    if (val >= 0.0f) atomicMax((int*)addr, __float_as_int(val));
    else             atomicMin((unsigned int*)addr, __float_as_uint(val));
}

__device__ __forceinline__ float to_tf32(float x) {
    float r; asm("cvt.rna.tf32.f32 %0, %1;" : "=f"(r) : "f"(x)); return r;
}

__device__ __forceinline__ void mma_tf32(float* c, const float* a, const float* b) {
    asm volatile(
        "mma.sync.aligned.m16n8k8.row.col.f32.tf32.tf32.f32 "
        "{%0,%1,%2,%3}, {%4,%5,%6,%7}, {%8,%9}, {%0,%1,%2,%3};"
        : "+f"(c[0]), "+f"(c[1]), "+f"(c[2]), "+f"(c[3])
        : "r"(__float_as_uint(a[0])), "r"(__float_as_uint(a[1])),
          "r"(__float_as_uint(a[2])), "r"(__float_as_uint(a[3])),
          "r"(__float_as_uint(b[0])), "r"(__float_as_uint(b[1])));
}

// ---------------- K0: init ----------------
__global__ void init_kernel() {
    int i = blockIdx.x * blockDim.x + threadIdx.x;
    if (i < 2 * NN) {
        g_amax[i] = __int_as_float(0xff800000);
        g_asum[i] = 0.0f;
    }
}

// =====================================================================
// tf32 GEMM tile: BM=128, BN=256, BK=32, 512 threads (16 warps, 4x4).
// Each warp: 32 rows x 64 cols -> acc[2][8][4]. Stride 36: conflict-free
// fragment LDS for the (g,i) pattern.
// =====================================================================
#define ASTR 36
#define BSTR 36
#define SMEM_BYTES ((128 * ASTR + 256 * BSTR) * 4)

// dynamic smem layout: A = base, B = base + 128*ASTR

__device__ __forceinline__ void fill_B(float* Bs, const float* __restrict__ W,
                                       int kt, int t) {
    int n = t & 255;
    int kh = t >> 8;            // 0..1, 16 k each
    #pragma unroll
    for (int j = 0; j < 16; j++) {
        Bs[n * BSTR + kh * 16 + j] = to_tf32(W[(size_t)(kt * 32 + kh * 16 + j) * 256 + n]);
    }
}

__device__ __forceinline__ void gemm_compute(const float* As, const float* Bs,
                                             float acc[2][8][4],
                                             int wm, int wn, int g, int i) {
    #pragma unroll
    for (int ks = 0; ks < 4; ks++) {
        int kb = ks * 8;
        float a[2][4];
        #pragma unroll
        for (int mm = 0; mm < 2; mm++) {
            int r = (wm * 32 + mm * 16 + g) * ASTR;
            a[mm][0] = As[r + kb + i];
            a[mm][1] = As[r + 8 * ASTR + kb + i];
            a[mm][2] = As[r + kb + i + 4];
            a[mm][3] = As[r + 8 * ASTR + kb + i + 4];
        }
        float b[8][2];
        #pragma unroll
        for (int nn = 0; nn < 8; nn++) {
            int cb = (wn * 64 + nn * 8 + g) * BSTR;
            b[nn][0] = Bs[cb + kb + i];
            b[nn][1] = Bs[cb + kb + i + 4];
        }
        #pragma unroll
        for (int mm = 0; mm < 2; mm++)
            #pragma unroll
            for (int nn = 0; nn < 8; nn++)
                mma_tf32(acc[mm][nn], a[mm], b[nn]);
    }
}

// ---------------- K1: node projections (tf32, BN=256) ----------------
__global__ __launch_bounds__(512) void node_proj_kernel(
    const float* __restrict__ x,
    const float* __restrict__ Wq, const float* __restrict__ bq,
    const float* __restrict__ Wk, const float* __restrict__ bk,
    const float* __restrict__ Wv, const float* __restrict__ bv,
    const float* __restrict__ Wskip, const float* __restrict__ bskip,
    float* __restrict__ out)
{
    extern __shared__ float smem[];
    float* As = smem;
    float* Bs = smem + 128 * ASTR;

    const int wsel = blockIdx.x;
    const int m0 = blockIdx.y * 128;

    const float* W; const float* bias; float* dst;
    switch (wsel) {
        case 0:  W = Wq;    bias = bq;    dst = g_q; break;
        case 1:  W = Wk;    bias = bk;    dst = g_k; break;
        case 2:  W = Wv;    bias = bv;    dst = g_v; break;
        default: W = Wskip; bias = bskip; dst = out; break;
    }

    const int t = threadIdx.x;
    const int warp = t >> 5, lane = t & 31;
    const int wm = warp >> 2, wn = warp & 3;
    const int g = lane >> 2, i = lane & 3;
    const int arow = t >> 2, q = t & 3;          // A fill: 8 k per thread
    int rowg = m0 + arow; if (rowg >= NN) rowg = NN - 1;

    float acc[2][8][4];
    #pragma unroll
    for (int mm = 0; mm < 2; mm++)
        #pragma unroll
        for (int nn = 0; nn < 8; nn++)
            #pragma unroll
            for (int r = 0; r < 4; r++) acc[mm][nn][r] = 0.0f;

    for (int kt = 0; kt < 8; kt++) {
        const float4* ap = (const float4*)&x[(size_t)rowg * 256 + kt * 32 + q * 8];
        #pragma unroll
        for (int q4 = 0; q4 < 2; q4++) {
            float4 v = ap[q4];
            float4 o; o.x = to_tf32(v.x); o.y = to_tf32(v.y);
            o.z = to_tf32(v.z); o.w = to_tf32(v.w);
            *(float4*)&As[arow * ASTR + q * 8 + q4 * 4] = o;
        }
        fill_B(Bs, W, kt, t);
        __syncthreads();
        gemm_compute(As, Bs, acc, wm, wn, g, i);
        __syncthreads();
    }

    #pragma unroll
    for (int mm = 0; mm < 2; mm++) {
        #pragma unroll
        for (int nn = 0; nn < 8; nn++) {
            int cc = wn * 64 + nn * 8 + i * 2;
            float2 bv2 = *(const float2*)&bias[cc];
            int r0 = m0 + wm * 32 + mm * 16 + g;
            if (r0 < NN) {
                float2 o; o.x = acc[mm][nn][0] + bv2.x; o.y = acc[mm][nn][1] + bv2.y;
                *(float2*)&dst[(size_t)r0 * 256 + cc] = o;
            }
            if (r0 + 8 < NN) {
                float2 o; o.x = acc[mm][nn][2] + bv2.x; o.y = acc[mm][nn][3] + bv2.y;
                *(float2*)&dst[(size_t)(r0 + 8) * 256 + cc] = o;
            }
        }
    }
}

// ---------------- K2: edge GEMM (tf32, BN=256) + fused full alpha ------------
__global__ __launch_bounds__(512) void edge_kernel(
    const float* __restrict__ last_update, const float* __restrict__ t_arr,
    const float* __restrict__ msg, const int* __restrict__ ei,
    const float* __restrict__ Wt, const float* __restrict__ bt,
    const float* __restrict__ We)
{
    extern __shared__ float smem[];
    float* As = smem;
    float* Bs = smem + 128 * ASTR;

    __shared__ float s_rel[128];
    __shared__ int   s_src[128], s_dst[128];
    __shared__ float s_wt[128], s_bt[128];
    __shared__ float s_alpha[256];               // [row][head]

    const int m0 = blockIdx.y * 128;             // EE % 128 == 0

    const int t = threadIdx.x;
    const int warp = t >> 5, lane = t & 31;
    const int wm = warp >> 2, wn = warp & 3;
    const int g = lane >> 2, i = lane & 3;
    const int arow = t >> 2, q = t & 3;
    const int eg = m0 + arow;

    if (t < 128) {
        s_wt[t] = Wt[t]; s_bt[t] = bt[t];
        int e = m0 + t;
        int sidx = ei[e];
        s_src[t] = sidx;
        s_dst[t] = ei[EE + e];
        s_rel[t] = last_update[sidx] - t_arr[e];
    }
    if (t < 256) s_alpha[t] = 0.0f;
    __syncthreads();

    const float rel = s_rel[arow];

    float acc[2][8][4];
    #pragma unroll
    for (int mm = 0; mm < 2; mm++)
        #pragma unroll
        for (int nn = 0; nn < 8; nn++)
            #pragma unroll
            for (int r = 0; r < 4; r++) acc[mm][nn][r] = 0.0f;

    for (int kt = 0; kt < 8; kt++) {
        if (kt < 4) {
            #pragma unroll
            for (int q4 = 0; q4 < 2; q4++) {
                int k = kt * 32 + q * 8 + q4 * 4;
                float4 o;
                o.x = to_tf32(__cosf(rel * s_wt[k + 0] + s_bt[k + 0]));
                o.y = to_tf32(__cosf(rel * s_wt[k + 1] + s_bt[k + 1]));
                o.z = to_tf32(__cosf(rel * s_wt[k + 2] + s_bt[k + 2]));
                o.w = to_tf32(__cosf(rel * s_wt[k + 3] + s_bt[k + 3]));
                *(float4*)&As[arow * ASTR + q * 8 + q4 * 4] = o;
            }
        } else {
            const float4* mp = (const float4*)&msg[(size_t)eg * 128 + (kt - 4) * 32 + q * 8];
            #pragma unroll
            for (int q4 = 0; q4 < 2; q4++) {
                float4 v = mp[q4];
                float4 o; o.x = to_tf32(v.x); o.y = to_tf32(v.y);
                o.z = to_tf32(v.z); o.w = to_tf32(v.w);
                *(float4*)&As[arow * ASTR + q * 8 + q4 * 4] = o;
            }
        }
        fill_B(Bs, We, kt, t);
        __syncthreads();
        gemm_compute(As, Bs, acc, wm, wn, g, i);
        __syncthreads();
    }

    // epilogue: store e; accumulate alpha partials in smem (warp is wholly in
    // head wn>>1), then finalize: scale, write g_alpha, segment-max.
    const int head = wn >> 1;
    #pragma unroll
    for (int mm = 0; mm < 2; mm++) {
        int lr = wm * 32 + mm * 16 + g;
        int e0 = m0 + lr, e1 = e0 + 8;
        int s0 = s_src[lr], d0 = s_dst[lr];
        int s1 = s_src[lr + 8], d1 = s_dst[lr + 8];
        float pa = 0.0f, pb = 0.0f;
        #pragma unroll
        for (int nn = 0; nn < 8; nn++) {
            int cc = wn * 64 + nn * 8 + i * 2;
            float2 ev0; ev0.x = acc[mm][nn][0]; ev0.y = acc[mm][nn][1];
            float2 ev1; ev1.x = acc[mm][nn][2]; ev1.y = acc[mm][nn][3];
            *(float2*)&g_e[(size_t)e0 * 256 + cc] = ev0;
            *(float2*)&g_e[(size_t)e1 * 256 + cc] = ev1;
            float2 q0 = *(const float2*)&g_q[(size_t)d0 * 256 + cc];
            float2 k0 = *(const float2*)&g_k[(size_t)s0 * 256 + cc];
            float2 q1 = *(const float2*)&g_q[(size_t)d1 * 256 + cc];
            float2 k1 = *(const float2*)&g_k[(size_t)s1 * 256 + cc];
            pa += q0.x * (k0.x + ev0.x) + q0.y * (k0.y + ev0.y);
            pb += q1.x * (k1.x + ev1.x) + q1.y * (k1.y + ev1.y);
        }
        pa += __shfl_xor_sync(0xffffffffu, pa, 1);
        pa += __shfl_xor_sync(0xffffffffu, pa, 2);
        pb += __shfl_xor_sync(0xffffffffu, pb, 1);
        pb += __shfl_xor_sync(0xffffffffu, pb, 2);
        if (i == 0) {
            atomicAdd(&s_alpha[lr * 2 + head], pa);
            atomicAdd(&s_alpha[(lr + 8) * 2 + head], pb);
        }
    }
    __syncthreads();

    if (t < 256) {
        int row = t >> 1, h = t & 1;
        float a = s_alpha[t] * 0.08838834764831845f;   // 1/sqrt(128)
        g_alpha[(size_t)(m0 + row) * 2 + h] = a;
        atomicMaxFloat(&g_amax[s_dst[row] * 2 + h], a);
    }
}

// ---------------- K3: exp + segment sum ----------------
__global__ void alpha_exp_kernel(const int* __restrict__ ei) {
    int idx = blockIdx.x * blockDim.x + threadIdx.x;
    if (idx >= 2 * EE) return;
    int e = idx >> 1, h = idx & 1;
    int d = ei[EE + e];
    float w = __expf(g_alpha[idx] - g_amax[d * 2 + h]);
    g_alpha[idx] = w;
    atomicAdd(&g_asum[d * 2 + h], w);
}

// ---------------- K4: weighted aggregate (vector RED) ----------------
__global__ __launch_bounds__(256) void aggregate_kernel(
    const int* __restrict__ ei, float* __restrict__ out)
{
    int warp = (int)((blockIdx.x * (unsigned)blockDim.x + threadIdx.x) >> 5);
    int lane = threadIdx.x & 31;
    if (warp >= EE) return;
    int e = warp;
    int sidx = ei[e];
    int didx = ei[EE + e];
    int col = lane * 8;
    int h = col >> 7;
    float coef = g_alpha[(size_t)e * 2 + h] / (g_asum[didx * 2 + h] + 1e-16f);
    const float4* vp = (const float4*)&g_v[(size_t)sidx * 256 + col];
    const float4* ep = (const float4*)&g_e[(size_t)e * 256 + col];
    float* op = &out[(size_t)didx * 256 + col];
    #pragma unroll
    for (int r = 0; r < 2; r++) {
        float4 vv = vp[r];
        float4 ev = ep[r];
        float a0 = (vv.x + ev.x) * coef;
        float a1 = (vv.y + ev.y) * coef;
        float a2 = (vv.z + ev.z) * coef;
        float a3 = (vv.w + ev.w) * coef;
        asm volatile("red.global.add.v4.f32 [%0], {%1, %2, %3, %4};"
                     :: "l"(op + r * 4), "f"(a0), "f"(a1), "f"(a2), "f"(a3)
                     : "memory");
    }
}

// ---------------- launcher ----------------
extern "C" void kernel_launch(void* const* d_in, const int* in_sizes, int n_in,
                              void* d_out, int out_size) {
    const float* x           = (const float*)d_in[0];
    const float* last_update = (const float*)d_in[1];
    const float* t_arr       = (const float*)d_in[2];
    const float* msg         = (const float*)d_in[3];
    const int*   ei          = (const int*)d_in[4];
    const float* Wt          = (const float*)d_in[5];
    const float* bt          = (const float*)d_in[6];
    const float* Wq          = (const float*)d_in[7];
    const float* bq          = (const float*)d_in[8];
    const float* Wk          = (const float*)d_in[9];
    const float* bk          = (const float*)d_in[10];
    const float* Wv          = (const float*)d_in[11];
    const float* bv          = (const float*)d_in[12];
    const float* We          = (const float*)d_in[13];
    const float* Wskip       = (const float*)d_in[14];
    const float* bskip       = (const float*)d_in[15];
    float* out = (float*)d_out;

    cudaFuncSetAttribute(node_proj_kernel,
                         cudaFuncAttributeMaxDynamicSharedMemorySize, SMEM_BYTES);
    cudaFuncSetAttribute(edge_kernel,
                         cudaFuncAttributeMaxDynamicSharedMemorySize, SMEM_BYTES);

    init_kernel<<<(2 * NN + 255) / 256, 256>>>();

    dim3 g1(4, (NN + 127) / 128);
    node_proj_kernel<<<g1, 512, SMEM_BYTES>>>(x, Wq, bq, Wk, bk, Wv, bv, Wskip, bskip, out);

    dim3 g2(1, EE / 128);
    edge_kernel<<<g2, 512, SMEM_BYTES>>>(last_update, t_arr, msg, ei, Wt, bt, We);

    alpha_exp_kernel<<<(2 * EE + 255) / 256, 256>>>(ei);
    aggregate_kernel<<<(EE * 32 + 255) / 256, 256>>>(ei, out);
}